// round 4
// baseline (speedup 1.0000x reference)
#include <cuda_runtime.h>
#include <cuda_fp16.h>
#include <mma.h>
#include <math.h>

using namespace nvcuda;

#define N_NODES 100000
#define N_EDGES 2000000

// ---------------- scratch (static device globals; no allocation) ----------------
__device__ __align__(256) float  g_h[N_NODES * 64];     // node hidden state (fp32)
__device__ __align__(256) __half g_AB[N_NODES * 256];   // per node: A0|B0|A1|B1 (64 each, fp16)
__device__ __align__(256) float  g_acc[N_NODES * 128];  // per node: acc_e0|acc_e1 (fp32)
__device__ __align__(256) float  g_agg[N_NODES * 64];   // aggregated message after W2
__device__ __align__(256) float  g_gh[N_NODES * 192];   // h @ gru_wh + bh
__device__ __align__(256) int    g_cnt[N_NODES * 2];    // per (node, edge_type) in-degree

// ---------------- input projection: h = relu(LN(x@in_w + in_b)) ----------------
__global__ void k_input(const float* __restrict__ x, const float* __restrict__ in_w,
                        const float* __restrict__ in_b, const float* __restrict__ ln_g,
                        const float* __restrict__ ln_b) {
    int n = blockIdx.x * blockDim.x + threadIdx.x;
    if (n >= N_NODES) return;
    float x0 = x[n * 4 + 0], x1 = x[n * 4 + 1], x2 = x[n * 4 + 2], x3 = x[n * 4 + 3];
    float hb[64];
    float mean = 0.f;
#pragma unroll
    for (int j = 0; j < 64; j++) {
        float s = in_b[j] + x0 * in_w[j] + x1 * in_w[64 + j] + x2 * in_w[128 + j] + x3 * in_w[192 + j];
        hb[j] = s;
        mean += s;
    }
    mean *= (1.f / 64.f);
    float var = 0.f;
#pragma unroll
    for (int j = 0; j < 64; j++) {
        float d = hb[j] - mean;
        var += d * d;
    }
    var *= (1.f / 64.f);
    float inv = rsqrtf(var + 1e-5f);
#pragma unroll
    for (int j = 0; j < 64; j++) {
        float v = (hb[j] - mean) * inv * ln_g[j] + ln_b[j];
        g_h[n * 64 + j] = v > 0.f ? v : 0.f;
    }
    g_cnt[n * 2 + 0] = 0;
    g_cnt[n * 2 + 1] = 0;
}

// ---------------- per-(dst,type) edge counts ------------------------------------
__global__ void k_cnt(const int* __restrict__ ei, const int* __restrict__ et) {
    int m = blockIdx.x * blockDim.x + threadIdx.x;
    if (m >= N_EDGES) return;
    int d = ei[N_EDGES + m];
    int e = et[m];
    atomicAdd(&g_cnt[d * 2 + e], 1);
}

// ---------------- tf32 WMMA block GEMM: C[64 x N] = A[64 x K] @ W[K x N] --------
// 256 threads = 8 warps. warp w: rowtile rt = w>>1 (16 rows), col half ch = w&1.
// As: 64 x LDA fp32 (LDA = K + 8 pad).  Ws: K x N fp32.  Cs: 64 x N fp32 (overlaps
// As/Ws after a syncthreads).
template <int K, int N>
__device__ __forceinline__ void wmma_block(const float* As, const float* Ws, float* Cs, int w) {
    constexpr int LDA = K + 8;
    constexpr int CT = N / 32;  // 16-wide col tiles per warp
    int rt = w >> 1;
    int colbase = (w & 1) * (N / 2);

    wmma::fragment<wmma::accumulator, 16, 16, 8, float> acc[CT];
#pragma unroll
    for (int c = 0; c < CT; c++) wmma::fill_fragment(acc[c], 0.0f);

#pragma unroll
    for (int kt = 0; kt < K / 8; kt++) {
        wmma::fragment<wmma::matrix_a, 16, 16, 8, wmma::precision::tf32, wmma::row_major> fa;
        wmma::load_matrix_sync(fa, As + rt * 16 * LDA + kt * 8, LDA);
#pragma unroll
        for (int i = 0; i < fa.num_elements; i++) fa.x[i] = wmma::__float_to_tf32(fa.x[i]);
#pragma unroll
        for (int c = 0; c < CT; c++) {
            wmma::fragment<wmma::matrix_b, 16, 16, 8, wmma::precision::tf32, wmma::row_major> fb;
            wmma::load_matrix_sync(fb, Ws + kt * 8 * N + colbase + c * 16, N);
#pragma unroll
            for (int i = 0; i < fb.num_elements; i++) fb.x[i] = wmma::__float_to_tf32(fb.x[i]);
            wmma::mma_sync(acc[c], fa, fb, acc[c]);
        }
    }
    __syncthreads();  // all reads of As/Ws done before Cs overwrites them
#pragma unroll
    for (int c = 0; c < CT; c++)
        wmma::store_matrix_sync(Cs + rt * 16 * N + colbase + c * 16, acc[c], N, wmma::mem_row_major);
    __syncthreads();
}

// load A tile (64 rows of width K from src, zero-padded past N_NODES)
template <int K>
__device__ __forceinline__ void load_A(float* As, const float* __restrict__ src, int base, int tid) {
    constexpr int LDA = K + 8;
    for (int idx = tid; idx < 64 * K; idx += 256) {
        int r = idx / K, k = idx % K;
        int n = base + r;
        As[r * LDA + k] = (n < N_NODES) ? src[(size_t)n * K + k] : 0.f;
    }
}

// ---------------- k_pre: AB = h @ [W1a0|W1b0|W1a1|W1b1] (+b1 on A), zero acc ----
__global__ __launch_bounds__(256) void k_pre(const float* __restrict__ w1,
                                             const float* __restrict__ b1, int l) {
    extern __shared__ float sm[];
    float* As = sm;                 // 64*72
    float* Ws = sm + 64 * 72;       // 64*256
    float* Cs = sm;                 // 64*256 (overlap)
    __shared__ float bs[256];
    int tid = threadIdx.x, w = tid >> 5;
    int base = blockIdx.x * 64;

    for (int idx = tid; idx < 64 * 256; idx += 256) {
        int k = idx >> 8, col = idx & 255;
        int e = col >> 7, part = (col >> 6) & 1, j = col & 63;
        int row = part ? (64 + k) : k;
        Ws[idx] = w1[((l * 2 + e) * 128 + row) * 64 + j];
    }
    {
        int col = tid;
        int e = col >> 7, part = (col >> 6) & 1, j = col & 63;
        bs[col] = part ? 0.f : b1[(l * 2 + e) * 64 + j];
    }
    load_A<64>(As, g_h, base, tid);
    __syncthreads();

    wmma_block<64, 256>(As, Ws, Cs, w);

    for (int idx = tid; idx < 64 * 256; idx += 256) {
        int r = idx >> 8, col = idx & 255;
        int n = base + r;
        if (n < N_NODES) g_AB[(size_t)n * 256 + col] = __float2half(Cs[idx] + bs[col]);
    }
    for (int idx = tid; idx < 64 * 128; idx += 256) {
        int r = idx >> 7, col = idx & 127;
        int n = base + r;
        if (n < N_NODES) g_acc[(size_t)n * 128 + col] = 0.f;
    }
}

// ---------------- k_edge: relu(A_e[src]+B_e[dst]) scattered into acc_e[dst] ----
__global__ __launch_bounds__(256) void k_edge(const int* __restrict__ ei,
                                              const int* __restrict__ et) {
    int gid = blockIdx.x * blockDim.x + threadIdx.x;
    int edge = gid >> 3;
    int t = gid & 7;  // 8 threads/edge, 8 features each
    if (edge >= N_EDGES) return;
    int s = ei[edge];
    int d = ei[N_EDGES + edge];
    int e = et[edge];

    const uint4* pa = reinterpret_cast<const uint4*>(g_AB + (size_t)s * 256 + e * 128) + t;
    const uint4* pb = reinterpret_cast<const uint4*>(g_AB + (size_t)d * 256 + e * 128 + 64) + t;
    uint4 ua = *pa;
    uint4 ub = *pb;
    const __half2* ha = reinterpret_cast<const __half2*>(&ua);
    const __half2* hb = reinterpret_cast<const __half2*>(&ub);

    float o[8];
#pragma unroll
    for (int q = 0; q < 4; q++) {
        float2 fa = __half22float2(ha[q]);
        float2 fb = __half22float2(hb[q]);
        float v0 = fa.x + fb.x;
        float v1 = fa.y + fb.y;
        o[2 * q + 0] = v0 > 0.f ? v0 : 0.f;
        o[2 * q + 1] = v1 > 0.f ? v1 : 0.f;
    }
    float* dstp = g_acc + (size_t)d * 128 + e * 64 + t * 8;
    asm volatile("red.global.add.v4.f32 [%0], {%1, %2, %3, %4};" ::"l"(dstp),
                 "f"(o[0]), "f"(o[1]), "f"(o[2]), "f"(o[3])
                 : "memory");
    asm volatile("red.global.add.v4.f32 [%0], {%1, %2, %3, %4};" ::"l"(dstp + 4),
                 "f"(o[4]), "f"(o[5]), "f"(o[6]), "f"(o[7])
                 : "memory");
}

// ---------------- k_agg: agg = acc @ [W2_0;W2_1] + cnt_e * b2_e ----------------
__global__ __launch_bounds__(256) void k_agg(const float* __restrict__ w2,
                                             const float* __restrict__ b2, int l) {
    extern __shared__ float sm[];
    float* As = sm;                  // 64*136
    float* Ws = sm + 64 * 136;       // 128*64
    float* Cs = sm;                  // 64*64 (overlap)
    __shared__ float b2s[128];
    int tid = threadIdx.x, w = tid >> 5;
    int base = blockIdx.x * 64;

    for (int idx = tid; idx < 128 * 64; idx += 256) {
        int k = idx >> 6, j = idx & 63;
        int e = k >> 6, kk = k & 63;
        Ws[idx] = w2[((l * 2 + e) * 64 + kk) * 64 + j];
    }
    if (tid < 128) b2s[tid] = b2[(l * 2 + (tid >> 6)) * 64 + (tid & 63)];
    load_A<128>(As, g_acc, base, tid);
    __syncthreads();

    wmma_block<128, 64>(As, Ws, Cs, w);

    for (int idx = tid; idx < 64 * 64; idx += 256) {
        int r = idx >> 6, j = idx & 63;
        int n = base + r;
        if (n < N_NODES) {
            float c0 = (float)g_cnt[n * 2 + 0];
            float c1 = (float)g_cnt[n * 2 + 1];
            g_agg[(size_t)n * 64 + j] = Cs[idx] + c0 * b2s[j] + c1 * b2s[64 + j];
        }
    }
}

// ---------------- k_gh: gh = h @ gru_wh[l] + bh ---------------------------------
__global__ __launch_bounds__(256) void k_gh(const float* __restrict__ wh,
                                            const float* __restrict__ bh, int l) {
    extern __shared__ float sm[];
    float* As = sm;                 // 64*72
    float* Ws = sm + 64 * 72;       // 64*192
    float* Cs = sm;                 // 64*192 (overlap)
    __shared__ float bhs[192];
    int tid = threadIdx.x, w = tid >> 5;
    int base = blockIdx.x * 64;

    for (int idx = tid; idx < 64 * 192; idx += 256) Ws[idx] = wh[l * 64 * 192 + idx];
    if (tid < 192) bhs[tid] = bh[l * 192 + tid];
    load_A<64>(As, g_h, base, tid);
    __syncthreads();

    wmma_block<64, 192>(As, Ws, Cs, w);

    for (int idx = tid; idx < 64 * 192; idx += 256) {
        int r = idx / 192, col = idx % 192;
        int n = base + r;
        if (n < N_NODES) g_gh[(size_t)n * 192 + col] = Cs[idx] + bhs[col];
    }
}

// ---------------- k_gi_gru: gi = agg @ gru_wi[l] + bi, then GRU update ----------
__global__ __launch_bounds__(256) void k_gi_gru(const float* __restrict__ wi,
                                                const float* __restrict__ bi, int l) {
    extern __shared__ float sm[];
    float* As = sm;                 // 64*72 (agg)
    float* Ws = sm + 64 * 72;       // 64*192
    float* Cs = sm;                 // 64*192 (overlap)
    __shared__ float bis[192];
    int tid = threadIdx.x, w = tid >> 5;
    int base = blockIdx.x * 64;

    for (int idx = tid; idx < 64 * 192; idx += 256) Ws[idx] = wi[l * 64 * 192 + idx];
    if (tid < 192) bis[tid] = bi[l * 192 + tid];
    load_A<64>(As, g_agg, base, tid);
    __syncthreads();

    wmma_block<64, 192>(As, Ws, Cs, w);

    for (int idx = tid; idx < 64 * 64; idx += 256) {
        int r = idx >> 6, j = idx & 63;
        int n = base + r;
        if (n >= N_NODES) continue;
        float vr = Cs[r * 192 + j] + bis[j];
        float vz = Cs[r * 192 + 64 + j] + bis[64 + j];
        float vn = Cs[r * 192 + 128 + j] + bis[128 + j];
        float gr = g_gh[(size_t)n * 192 + j];
        float gz = g_gh[(size_t)n * 192 + 64 + j];
        float gn = g_gh[(size_t)n * 192 + 128 + j];
        float rr = 1.f / (1.f + expf(-(vr + gr)));
        float zz = 1.f / (1.f + expf(-(vz + gz)));
        float nn = tanhf(vn + rr * gn);
        float ho = g_h[(size_t)n * 64 + j];
        g_h[(size_t)n * 64 + j] = (1.f - zz) * nn + zz * ho;
    }
}

// ---------------- k_ro: out = relu(h@ro_w1+b1)@ro_w2+b2; corr write -------------
__global__ __launch_bounds__(256) void k_ro(const float* __restrict__ w1,
                                            const float* __restrict__ b1,
                                            const float* __restrict__ w2,
                                            const float* __restrict__ b2,
                                            const int* __restrict__ node_type,
                                            const float* __restrict__ x,
                                            float* __restrict__ out) {
    extern __shared__ float sm[];
    float* As = sm;                // 64*72
    float* Ws = sm + 64 * 72;      // 64*64
    float* Cs = sm;                // 64*64 (overlap)
    __shared__ float b1s[64];
    __shared__ float w2s[64];
    int tid = threadIdx.x, w = tid >> 5;
    int base = blockIdx.x * 64;

    for (int idx = tid; idx < 64 * 64; idx += 256) Ws[idx] = w1[idx];
    if (tid < 64) { b1s[tid] = b1[tid]; w2s[tid] = w2[tid]; }
    load_A<64>(As, g_h, base, tid);
    __syncthreads();

    wmma_block<64, 64>(As, Ws, Cs, w);

    // 4 threads per row reduce 64 cols
    for (int idx = tid; idx < 64 * 4; idx += 256) {
        int r = idx >> 2, part = idx & 3;
        int n = base + r;
        if (n >= N_NODES) continue;
        float p = 0.f;
#pragma unroll
        for (int q = 0; q < 16; q++) {
            int j = part * 16 + q;
            float t = Cs[r * 64 + j] + b1s[j];
            t = t > 0.f ? t : 0.f;
            p += t * w2s[j];
        }
        // combine 4 partials via shared atomics-free shuffle within warp:
        // lanes with same r are adjacent (idx contiguous) => use __shfl_down
        unsigned mask = __activemask();
        p += __shfl_down_sync(mask, p, 1);
        p += __shfl_down_sync(mask, p, 2);
        if (part == 0) {
            float o = p + b2[0];
            out[n] = (node_type[n] == 0) ? (x[n * 4] + o) : 0.f;
        }
    }
}

// ---------------- launch ---------------------------------------------------------
extern "C" void kernel_launch(void* const* d_in, const int* in_sizes, int n_in,
                              void* d_out, int out_size) {
    const float* x        = (const float*)d_in[0];
    const int*   node_ty  = (const int*)d_in[1];
    const int*   ei       = (const int*)d_in[2];
    const int*   et       = (const int*)d_in[3];
    const float* in_w     = (const float*)d_in[4];
    const float* in_b     = (const float*)d_in[5];
    const float* ln_g     = (const float*)d_in[6];
    const float* ln_b     = (const float*)d_in[7];
    const float* mlp_w1   = (const float*)d_in[8];
    const float* mlp_b1   = (const float*)d_in[9];
    const float* mlp_w2   = (const float*)d_in[10];
    const float* mlp_b2   = (const float*)d_in[11];
    const float* gru_wi   = (const float*)d_in[12];
    const float* gru_wh   = (const float*)d_in[13];
    const float* gru_bi   = (const float*)d_in[14];
    const float* gru_bh   = (const float*)d_in[15];
    const float* ro_w1    = (const float*)d_in[16];
    const float* ro_b1    = (const float*)d_in[17];
    const float* ro_w2    = (const float*)d_in[18];
    const float* ro_b2    = (const float*)d_in[19];
    float* out = (float*)d_out;

    const int SM_PRE = (64 * 72 + 64 * 256) * 4;
    const int SM_AGG = (64 * 136 + 128 * 64) * 4;
    const int SM_G   = (64 * 72 + 64 * 192) * 4;
    const int SM_RO  = (64 * 72 + 64 * 64) * 4;

    cudaFuncSetAttribute(k_pre,    cudaFuncAttributeMaxDynamicSharedMemorySize, 100 * 1024);
    cudaFuncSetAttribute(k_agg,    cudaFuncAttributeMaxDynamicSharedMemorySize, 100 * 1024);
    cudaFuncSetAttribute(k_gh,     cudaFuncAttributeMaxDynamicSharedMemorySize, 100 * 1024);
    cudaFuncSetAttribute(k_gi_gru, cudaFuncAttributeMaxDynamicSharedMemorySize, 100 * 1024);
    cudaFuncSetAttribute(k_ro,     cudaFuncAttributeMaxDynamicSharedMemorySize, 100 * 1024);

    const int NB = (N_NODES + 63) / 64;

    k_input<<<(N_NODES + 127) / 128, 128>>>(x, in_w, in_b, ln_g, ln_b);
    k_cnt<<<(N_EDGES + 255) / 256, 256>>>(ei, et);

    for (int l = 0; l < 3; l++) {
        k_pre<<<NB, 256, SM_PRE>>>(mlp_w1, mlp_b1, l);
        k_edge<<<(N_EDGES * 8 + 255) / 256, 256>>>(ei, et);
        k_agg<<<NB, 256, SM_AGG>>>(mlp_w2, mlp_b2, l);
        k_gh<<<NB, 256, SM_G>>>(gru_wh, gru_bh, l);
        k_gi_gru<<<NB, 256, SM_G>>>(gru_wi, gru_bi, l);
    }
    k_ro<<<NB, 256, SM_RO>>>(ro_w1, ro_b1, ro_w2, ro_b2, node_ty, x, out);
}